// round 1
// baseline (speedup 1.0000x reference)
#include <cuda_runtime.h>
#include <cuda_bf16.h>
#include <math.h>

// Problem constants (fixed by reference: B=16, C=512, H=W=32, GROUPS=32)
#define BB   16
#define CC   512
#define NN_  1024          // H*W
#define CG   16            // C / GROUPS
#define SCALE 0.044194173824159216f   // 512^-0.5

// ---------------------------------------------------------------------------
// Scratch (device globals; no runtime allocation allowed)
// ---------------------------------------------------------------------------
__device__ float g_xn  [(size_t)BB * CC * NN_];        //  32 MB  normalized x
__device__ float g_qkv [(size_t)BB * 3 * CC * NN_];    //  96 MB  qkv
__device__ float g_attn[(size_t)BB * NN_ * NN_];       //  64 MB  attention matrix
__device__ float g_av  [(size_t)BB * CC * NN_];        //  32 MB  attention output

// ---------------------------------------------------------------------------
// GroupNorm: one block per (batch, group). Group data is 16384 contiguous floats.
// ---------------------------------------------------------------------------
__global__ void gn_kernel(const float* __restrict__ x,
                          const float* __restrict__ gamma,
                          const float* __restrict__ beta) {
    const int b = blockIdx.x >> 5;
    const int g = blockIdx.x & 31;
    const size_t base = ((size_t)b * CC + (size_t)g * CG) * NN_;
    const float4* __restrict__ x4 = (const float4*)(x + base);

    float s = 0.f, s2 = 0.f;
    const int n4 = CG * NN_ / 4;   // 4096 float4s
    for (int i = threadIdx.x; i < n4; i += 256) {
        float4 v = x4[i];
        s  += v.x + v.y + v.z + v.w;
        s2 += v.x * v.x + v.y * v.y + v.z * v.z + v.w * v.w;
    }
    #pragma unroll
    for (int o = 16; o; o >>= 1) {
        s  += __shfl_down_sync(0xffffffffu, s,  o);
        s2 += __shfl_down_sync(0xffffffffu, s2, o);
    }
    __shared__ float2 sh[8];
    __shared__ float mu_s, rstd_s;
    if ((threadIdx.x & 31) == 0) sh[threadIdx.x >> 5] = make_float2(s, s2);
    __syncthreads();
    if (threadIdx.x == 0) {
        float ts = 0.f, ts2 = 0.f;
        #pragma unroll
        for (int i = 0; i < 8; i++) { ts += sh[i].x; ts2 += sh[i].y; }
        const float inv = 1.f / (float)(CG * NN_);
        float mu  = ts * inv;
        float var = ts2 * inv - mu * mu;
        mu_s = mu;
        rstd_s = rsqrtf(var + 1e-5f);
    }
    __syncthreads();
    const float mu = mu_s, rstd = rstd_s;

    float4* __restrict__ o4 = (float4*)(g_xn + base);
    for (int i = threadIdx.x; i < n4; i += 256) {
        const int c = g * CG + (i >> 8);               // i*4/1024
        const float ga = gamma[c] * rstd;
        const float be = beta[c] - mu * ga;
        float4 v = x4[i];
        v.x = v.x * ga + be; v.y = v.y * ga + be;
        v.z = v.z * ga + be; v.w = v.w * ga + be;
        o4[i] = v;
    }
}

// ---------------------------------------------------------------------------
// GEMM 1: qkv[b][o][n] = sum_c W[o][c] * xn[b][c][n] + bias[o]
// A = W (M=1536, K=512) row-major ; B = xn[b] (K=512, N=1024) row-major.
// 64x64 tile, BK=16, 256 threads, 4x4 per thread.
// ---------------------------------------------------------------------------
__global__ void gemm_qkv(const float* __restrict__ W,
                         const float* __restrict__ bias) {
    const int b  = blockIdx.z;
    const float* __restrict__ Bp = g_xn + (size_t)b * CC * NN_;
    float* __restrict__ Op = g_qkv + (size_t)b * 3 * CC * NN_;
    const int m0 = blockIdx.y * 64, n0 = blockIdx.x * 64;

    __shared__ float As[16][65];
    __shared__ float Bs[16][68];

    const int tid = threadIdx.x;
    const int tx = tid & 15, ty = tid >> 4;
    float acc[4][4] = {};

    const int a_mm = tid >> 2, a_kk = (tid & 3) * 4;
    const int b_kk = tid >> 4, b_nn = (tid & 15) * 4;

    for (int k0 = 0; k0 < CC; k0 += 16) {
        float4 va = *(const float4*)(W + (size_t)(m0 + a_mm) * CC + k0 + a_kk);
        As[a_kk + 0][a_mm] = va.x; As[a_kk + 1][a_mm] = va.y;
        As[a_kk + 2][a_mm] = va.z; As[a_kk + 3][a_mm] = va.w;
        float4 vb = *(const float4*)(Bp + (size_t)(k0 + b_kk) * NN_ + n0 + b_nn);
        *(float4*)&Bs[b_kk][b_nn] = vb;
        __syncthreads();
        #pragma unroll
        for (int kk = 0; kk < 16; kk++) {
            float a[4], bb[4];
            #pragma unroll
            for (int r = 0; r < 4; r++) a[r] = As[kk][ty + 16 * r];
            #pragma unroll
            for (int c = 0; c < 4; c++) bb[c] = Bs[kk][tx + 16 * c];
            #pragma unroll
            for (int r = 0; r < 4; r++)
                #pragma unroll
                for (int c = 0; c < 4; c++) acc[r][c] += a[r] * bb[c];
        }
        __syncthreads();
    }
    #pragma unroll
    for (int r = 0; r < 4; r++) {
        const int m = m0 + ty + 16 * r;
        const float bm = bias[m];
        #pragma unroll
        for (int c = 0; c < 4; c++)
            Op[(size_t)m * NN_ + n0 + tx + 16 * c] = acc[r][c] + bm;
    }
}

// ---------------------------------------------------------------------------
// GEMM 2 (TN): attn[b][i][j] = SCALE * sum_c q[b][c][i] * k[b][c][j]
// Both operands stored (K=C, M/N) -> coalesced direct loads.
// ---------------------------------------------------------------------------
__global__ void gemm_scores() {
    const int b = blockIdx.z;
    const float* __restrict__ Qp = g_qkv + (size_t)b * 3 * CC * NN_;
    const float* __restrict__ Kp = Qp + (size_t)CC * NN_;
    float* __restrict__ Sp = g_attn + (size_t)b * NN_ * NN_;
    const int m0 = blockIdx.y * 64, n0 = blockIdx.x * 64;

    __shared__ float As[16][68];
    __shared__ float Bs[16][68];

    const int tid = threadIdx.x;
    const int tx = tid & 15, ty = tid >> 4;
    float acc[4][4] = {};

    const int l_kk = tid >> 4, l_mm = (tid & 15) * 4;

    for (int k0 = 0; k0 < CC; k0 += 16) {
        float4 va = *(const float4*)(Qp + (size_t)(k0 + l_kk) * NN_ + m0 + l_mm);
        *(float4*)&As[l_kk][l_mm] = va;
        float4 vb = *(const float4*)(Kp + (size_t)(k0 + l_kk) * NN_ + n0 + l_mm);
        *(float4*)&Bs[l_kk][l_mm] = vb;
        __syncthreads();
        #pragma unroll
        for (int kk = 0; kk < 16; kk++) {
            float a[4], bb[4];
            #pragma unroll
            for (int r = 0; r < 4; r++) a[r] = As[kk][ty + 16 * r];
            #pragma unroll
            for (int c = 0; c < 4; c++) bb[c] = Bs[kk][tx + 16 * c];
            #pragma unroll
            for (int r = 0; r < 4; r++)
                #pragma unroll
                for (int c = 0; c < 4; c++) acc[r][c] += a[r] * bb[c];
        }
        __syncthreads();
    }
    #pragma unroll
    for (int r = 0; r < 4; r++) {
        const int m = m0 + ty + 16 * r;
        #pragma unroll
        for (int c = 0; c < 4; c++)
            Sp[(size_t)m * NN_ + n0 + tx + 16 * c] = acc[r][c] * SCALE;
    }
}

// ---------------------------------------------------------------------------
// Softmax over last dim. One block (256 thr) per row of 1024 -> one float4/thread.
// ---------------------------------------------------------------------------
__global__ void softmax_kernel() {
    float4* __restrict__ row = (float4*)(g_attn + (size_t)blockIdx.x * NN_);
    float4 v = row[threadIdx.x];

    float m = fmaxf(fmaxf(v.x, v.y), fmaxf(v.z, v.w));
    #pragma unroll
    for (int o = 16; o; o >>= 1) m = fmaxf(m, __shfl_xor_sync(0xffffffffu, m, o));
    __shared__ float shm[8], shs[8];
    if ((threadIdx.x & 31) == 0) shm[threadIdx.x >> 5] = m;
    __syncthreads();
    float M = shm[0];
    #pragma unroll
    for (int i = 1; i < 8; i++) M = fmaxf(M, shm[i]);

    v.x = __expf(v.x - M); v.y = __expf(v.y - M);
    v.z = __expf(v.z - M); v.w = __expf(v.w - M);
    float s = v.x + v.y + v.z + v.w;
    #pragma unroll
    for (int o = 16; o; o >>= 1) s += __shfl_xor_sync(0xffffffffu, s, o);
    if ((threadIdx.x & 31) == 0) shs[threadIdx.x >> 5] = s;
    __syncthreads();
    float S = 0.f;
    #pragma unroll
    for (int i = 0; i < 8; i++) S += shs[i];
    const float r = 1.f / S;
    v.x *= r; v.y *= r; v.z *= r; v.w *= r;
    row[threadIdx.x] = v;
}

// ---------------------------------------------------------------------------
// GEMM 3 (NT): av[b][c][i] = sum_j V[b][c][j] * attn[b][i][j]
// A = V (M=512, K=1024) row-major; B = attn accessed transposed (N=i, K=j).
// ---------------------------------------------------------------------------
__global__ void gemm_av() {
    const int b = blockIdx.z;
    const float* __restrict__ Vp = g_qkv + (size_t)b * 3 * CC * NN_ + (size_t)2 * CC * NN_;
    const float* __restrict__ Ap = g_attn + (size_t)b * NN_ * NN_;
    float* __restrict__ Op = g_av + (size_t)b * CC * NN_;
    const int m0 = blockIdx.y * 64, n0 = blockIdx.x * 64;

    __shared__ float As[16][65];
    __shared__ float Bs[16][65];

    const int tid = threadIdx.x;
    const int tx = tid & 15, ty = tid >> 4;
    float acc[4][4] = {};

    const int a_mm = tid >> 2, a_kk = (tid & 3) * 4;   // also reused for B (nn, kk)

    for (int k0 = 0; k0 < NN_; k0 += 16) {
        float4 va = *(const float4*)(Vp + (size_t)(m0 + a_mm) * NN_ + k0 + a_kk);
        As[a_kk + 0][a_mm] = va.x; As[a_kk + 1][a_mm] = va.y;
        As[a_kk + 2][a_mm] = va.z; As[a_kk + 3][a_mm] = va.w;
        float4 vb = *(const float4*)(Ap + (size_t)(n0 + a_mm) * NN_ + k0 + a_kk);
        Bs[a_kk + 0][a_mm] = vb.x; Bs[a_kk + 1][a_mm] = vb.y;
        Bs[a_kk + 2][a_mm] = vb.z; Bs[a_kk + 3][a_mm] = vb.w;
        __syncthreads();
        #pragma unroll
        for (int kk = 0; kk < 16; kk++) {
            float a[4], bb[4];
            #pragma unroll
            for (int r = 0; r < 4; r++) a[r] = As[kk][ty + 16 * r];
            #pragma unroll
            for (int c = 0; c < 4; c++) bb[c] = Bs[kk][tx + 16 * c];
            #pragma unroll
            for (int r = 0; r < 4; r++)
                #pragma unroll
                for (int c = 0; c < 4; c++) acc[r][c] += a[r] * bb[c];
        }
        __syncthreads();
    }
    #pragma unroll
    for (int r = 0; r < 4; r++) {
        const int m = m0 + ty + 16 * r;
        #pragma unroll
        for (int c = 0; c < 4; c++)
            Op[(size_t)m * NN_ + n0 + tx + 16 * c] = acc[r][c];
    }
}

// ---------------------------------------------------------------------------
// GEMM 4 (NN + bias + residual): y = x + b_proj + Wp @ av
// ---------------------------------------------------------------------------
__global__ void gemm_proj(const float* __restrict__ Wp,
                          const float* __restrict__ bias,
                          const float* __restrict__ x,
                          float* __restrict__ y) {
    const int b = blockIdx.z;
    const float* __restrict__ Bp = g_av + (size_t)b * CC * NN_;
    const float* __restrict__ Xp = x + (size_t)b * CC * NN_;
    float* __restrict__ Op = y + (size_t)b * CC * NN_;
    const int m0 = blockIdx.y * 64, n0 = blockIdx.x * 64;

    __shared__ float As[16][65];
    __shared__ float Bs[16][68];

    const int tid = threadIdx.x;
    const int tx = tid & 15, ty = tid >> 4;
    float acc[4][4] = {};

    const int a_mm = tid >> 2, a_kk = (tid & 3) * 4;
    const int b_kk = tid >> 4, b_nn = (tid & 15) * 4;

    for (int k0 = 0; k0 < CC; k0 += 16) {
        float4 va = *(const float4*)(Wp + (size_t)(m0 + a_mm) * CC + k0 + a_kk);
        As[a_kk + 0][a_mm] = va.x; As[a_kk + 1][a_mm] = va.y;
        As[a_kk + 2][a_mm] = va.z; As[a_kk + 3][a_mm] = va.w;
        float4 vb = *(const float4*)(Bp + (size_t)(k0 + b_kk) * NN_ + n0 + b_nn);
        *(float4*)&Bs[b_kk][b_nn] = vb;
        __syncthreads();
        #pragma unroll
        for (int kk = 0; kk < 16; kk++) {
            float a[4], bb[4];
            #pragma unroll
            for (int r = 0; r < 4; r++) a[r] = As[kk][ty + 16 * r];
            #pragma unroll
            for (int c = 0; c < 4; c++) bb[c] = Bs[kk][tx + 16 * c];
            #pragma unroll
            for (int r = 0; r < 4; r++)
                #pragma unroll
                for (int c = 0; c < 4; c++) acc[r][c] += a[r] * bb[c];
        }
        __syncthreads();
    }
    #pragma unroll
    for (int r = 0; r < 4; r++) {
        const int m = m0 + ty + 16 * r;
        const float bm = bias[m];
        #pragma unroll
        for (int c = 0; c < 4; c++) {
            const size_t idx = (size_t)m * NN_ + n0 + tx + 16 * c;
            Op[idx] = Xp[idx] + acc[r][c] + bm;
        }
    }
}

// ---------------------------------------------------------------------------
// Launch
// ---------------------------------------------------------------------------
extern "C" void kernel_launch(void* const* d_in, const int* in_sizes, int n_in,
                              void* d_out, int out_size) {
    const float* x      = (const float*)d_in[0];
    const float* gamma  = (const float*)d_in[1];
    const float* beta   = (const float*)d_in[2];
    const float* w_qkv  = (const float*)d_in[3];
    const float* b_qkv  = (const float*)d_in[4];
    const float* w_proj = (const float*)d_in[5];
    const float* b_proj = (const float*)d_in[6];
    float* y = (float*)d_out;

    gn_kernel<<<BB * 32, 256>>>(x, gamma, beta);
    gemm_qkv<<<dim3(NN_ / 64, (3 * CC) / 64, BB), 256>>>(w_qkv, b_qkv);
    gemm_scores<<<dim3(NN_ / 64, NN_ / 64, BB), 256>>>();
    softmax_kernel<<<BB * NN_, 256>>>();
    gemm_av<<<dim3(NN_ / 64, CC / 64, BB), 256>>>();
    gemm_proj<<<dim3(NN_ / 64, CC / 64, BB), 256>>>(w_proj, b_proj, x, y);
}

// round 3
// speedup vs baseline: 3.6400x; 3.6400x over previous
#include <cuda_runtime.h>
#include <cuda_bf16.h>
#include <math.h>
#include <stdint.h>

// Problem constants: B=16, C=512, H=W=32, GROUPS=32
#define BB   16
#define CC   512
#define NN_  1024
#define CG   16
#define SCALE 0.044194173824159216f   // 512^-0.5

// ---------------------------------------------------------------------------
// Scratch (device globals). All bf16 arrays are hi/lo split pairs.
// ---------------------------------------------------------------------------
__device__ __align__(128) __nv_bfloat16 g_xnh [(size_t)BB * NN_ * CC];   // xn_t [b][n][c]
__device__ __align__(128) __nv_bfloat16 g_xnl [(size_t)BB * NN_ * CC];
__device__ __align__(128) __nv_bfloat16 g_wqh [(size_t)3 * CC * CC];
__device__ __align__(128) __nv_bfloat16 g_wql [(size_t)3 * CC * CC];
__device__ __align__(128) __nv_bfloat16 g_wph [(size_t)CC * CC];
__device__ __align__(128) __nv_bfloat16 g_wpl [(size_t)CC * CC];
__device__ __align__(128) __nv_bfloat16 g_qkth[(size_t)BB * NN_ * NN_];  // [b][n][o] (q|k)
__device__ __align__(128) __nv_bfloat16 g_qktl[(size_t)BB * NN_ * NN_];
__device__ __align__(128) __nv_bfloat16 g_vh  [(size_t)BB * CC * NN_];   // v [b][c][n]
__device__ __align__(128) __nv_bfloat16 g_vl  [(size_t)BB * CC * NN_];
__device__ __align__(128) float         g_s   [(size_t)BB * NN_ * NN_];  // scores fp32
__device__ __align__(128) __nv_bfloat16 g_ah  [(size_t)BB * NN_ * NN_];  // attn split
__device__ __align__(128) __nv_bfloat16 g_al  [(size_t)BB * NN_ * NN_];
__device__ __align__(128) __nv_bfloat16 g_avh [(size_t)BB * NN_ * CC];   // av_t [b][n][c]
__device__ __align__(128) __nv_bfloat16 g_avl [(size_t)BB * NN_ * CC];

// ---------------------------------------------------------------------------
// Helpers (all base-target sm_80+ instructions; no 'a'-gated features)
// ---------------------------------------------------------------------------
__device__ __forceinline__ uint32_t smem_u32(const void* p) {
    uint32_t a;
    asm("{ .reg .u64 t; cvta.to.shared.u64 t, %1; cvt.u32.u64 %0, t; }" : "=r"(a) : "l"(p));
    return a;
}
__device__ __forceinline__ void ldsm4(uint32_t (&r)[4], uint32_t addr) {
    asm volatile("ldmatrix.sync.aligned.m8n8.x4.shared.b16 {%0,%1,%2,%3}, [%4];"
        : "=r"(r[0]), "=r"(r[1]), "=r"(r[2]), "=r"(r[3]) : "r"(addr));
}
__device__ __forceinline__ void ldsm2(uint32_t (&r)[2], uint32_t addr) {
    asm volatile("ldmatrix.sync.aligned.m8n8.x2.shared.b16 {%0,%1}, [%2];"
        : "=r"(r[0]), "=r"(r[1]) : "r"(addr));
}
__device__ __forceinline__ void mma16816(float (&c)[4], const uint32_t (&a)[4],
                                         const uint32_t (&b)[2]) {
    asm volatile("mma.sync.aligned.m16n8k16.row.col.f32.bf16.bf16.f32 "
        "{%0,%1,%2,%3}, {%4,%5,%6,%7}, {%8,%9}, {%0,%1,%2,%3};"
        : "+f"(c[0]), "+f"(c[1]), "+f"(c[2]), "+f"(c[3])
        : "r"(a[0]), "r"(a[1]), "r"(a[2]), "r"(a[3]), "r"(b[0]), "r"(b[1]));
}
__device__ __forceinline__ void cp16(uint32_t dst, const void* src) {
    asm volatile("cp.async.cg.shared.global [%0], [%1], 16;" :: "r"(dst), "l"(src));
}
__device__ __forceinline__ void cp_commit() {
    asm volatile("cp.async.commit_group;" ::: "memory");
}
template<int N> __device__ __forceinline__ void cp_wait() {
    asm volatile("cp.async.wait_group %0;" :: "n"(N) : "memory");
}

__device__ __forceinline__ void split2(float v, __nv_bfloat16& h, __nv_bfloat16& l) {
    h = __float2bfloat16(v);
    l = __float2bfloat16(v - __bfloat162float(h));
}

// ---------------------------------------------------------------------------
// Weight split: fp32 -> bf16 hi/lo
// ---------------------------------------------------------------------------
__global__ void split_kernel(const float* __restrict__ src,
                             __nv_bfloat16* __restrict__ dh,
                             __nv_bfloat16* __restrict__ dl, int n) {
    int i = blockIdx.x * blockDim.x + threadIdx.x;
    if (i < n) { __nv_bfloat16 h, l; split2(src[i], h, l); dh[i] = h; dl[i] = l; }
}

// ---------------------------------------------------------------------------
// GroupNorm -> transposed split output xn_t[b][n][c] (hi/lo)
// ---------------------------------------------------------------------------
__global__ void gn_kernel(const float* __restrict__ x,
                          const float* __restrict__ gamma,
                          const float* __restrict__ beta) {
    const int b = blockIdx.x >> 5;
    const int g = blockIdx.x & 31;
    const size_t base = ((size_t)b * CC + (size_t)g * CG) * NN_;
    const float4* __restrict__ x4 = (const float4*)(x + base);

    float s = 0.f, s2 = 0.f;
    for (int i = threadIdx.x; i < CG * NN_ / 4; i += 256) {
        float4 v = x4[i];
        s  += v.x + v.y + v.z + v.w;
        s2 += v.x * v.x + v.y * v.y + v.z * v.z + v.w * v.w;
    }
    #pragma unroll
    for (int o = 16; o; o >>= 1) {
        s  += __shfl_down_sync(0xffffffffu, s,  o);
        s2 += __shfl_down_sync(0xffffffffu, s2, o);
    }
    __shared__ float2 sh[8];
    __shared__ float sga[16], sbe[16];
    if ((threadIdx.x & 31) == 0) sh[threadIdx.x >> 5] = make_float2(s, s2);
    __syncthreads();
    if (threadIdx.x < 16) {
        float ts = 0.f, ts2 = 0.f;
        #pragma unroll
        for (int i = 0; i < 8; i++) { ts += sh[i].x; ts2 += sh[i].y; }
        const float inv = 1.f / (float)(CG * NN_);
        float mu  = ts * inv;
        float var = ts2 * inv - mu * mu;
        float rstd = rsqrtf(var + 1e-5f);
        int c = g * CG + threadIdx.x;
        float ga = gamma[c] * rstd;
        sga[threadIdx.x] = ga;
        sbe[threadIdx.x] = beta[c] - mu * ga;
    }
    __syncthreads();

    for (int n = threadIdx.x; n < NN_; n += 256) {
        __align__(16) __nv_bfloat16 hh[16], ll[16];
        #pragma unroll
        for (int c = 0; c < 16; c++) {
            float v = x[base + (size_t)c * NN_ + n];
            v = v * sga[c] + sbe[c];
            split2(v, hh[c], ll[c]);
        }
        size_t o = ((size_t)(b * NN_ + n)) * CC + g * CG;
        *(uint4*)(g_xnh + o)     = *(uint4*)(hh);
        *(uint4*)(g_xnh + o + 8) = *(uint4*)(hh + 8);
        *(uint4*)(g_xnl + o)     = *(uint4*)(ll);
        *(uint4*)(g_xnl + o + 8) = *(uint4*)(ll + 8);
    }
}

// ---------------------------------------------------------------------------
// Split-bf16 HMMA GEMM (mma.sync.m16n8k16.row.col).
// D[M,N] = sum_k A[m][k] * B[n][k]   (both K-major)
// CTA tile 128x128, BK=64 (128B rows, XOR swizzle), 8 warps (64x32 each),
// cp.async double-buffered. 3 products per K-chunk: AhBh + AhBl + AlBh.
// EPI: 0=split+col bias, 1=split+row bias, 2=fp32*SCALE, 3=split, 4=fp32+row bias+resid
// ---------------------------------------------------------------------------
#define STAGE_BYTES 65536              // 4 matrices x 16KB
#define SMEM_BYTES  (2 * STAGE_BYTES)

template<int EPI>
__global__ void __launch_bounds__(256, 1) gemm_bb(
    const __nv_bfloat16* __restrict__ Ah, const __nv_bfloat16* __restrict__ Al,
    size_t aBatch, int ldA,
    const __nv_bfloat16* __restrict__ Bh, const __nv_bfloat16* __restrict__ Bl,
    size_t bBatch, int ldB,
    int K,
    __nv_bfloat16* __restrict__ outH, __nv_bfloat16* __restrict__ outL,
    float* __restrict__ outF,
    size_t oBatch, int ldO,
    const float* __restrict__ bias, const float* __restrict__ resid)
{
    extern __shared__ char smem[];
    const uint32_t sb = smem_u32(smem);

    const int tid = threadIdx.x, lane = tid & 31, wid = tid >> 5;
    const int wm = wid >> 2, wn = wid & 3;       // 2 x 4 warp grid
    const int b  = blockIdx.z;
    const int m0 = blockIdx.y * 128, n0 = blockIdx.x * 128;

    const __nv_bfloat16* srcP[4] = {
        Ah + (size_t)b * aBatch + (size_t)m0 * ldA,
        Al + (size_t)b * aBatch + (size_t)m0 * ldA,
        Bh + (size_t)b * bBatch + (size_t)n0 * ldB,
        Bl + (size_t)b * bBatch + (size_t)n0 * ldB };
    const int lds_[4] = { ldA, ldA, ldB, ldB };

    // loader indexing: per matrix, 1024 16B-chunks (128 rows x 8), 4 waves of 256 thr
    const int l_row = (tid >> 3) & 127 ? 0 : 0;  // (placeholder, computed below)

    float acc[4][4][4];
    #pragma unroll
    for (int i = 0; i < 4; i++)
        #pragma unroll
        for (int j = 0; j < 4; j++)
            #pragma unroll
            for (int q = 0; q < 4; q++) acc[i][j][q] = 0.f;

    const int T = K / 64;

    // stage loader
    auto load_stage = [&](int t) {
        const int k0 = t * 64;
        const uint32_t sbuf = sb + (t & 1) * STAGE_BYTES;
        #pragma unroll
        for (int mat = 0; mat < 4; mat++) {
            const __nv_bfloat16* sp = srcP[mat];
            const int ld = lds_[mat];
            #pragma unroll
            for (int q = 0; q < 4; q++) {
                const int c = q * 256 + tid;       // 0..1023
                const int row = c >> 3, g = c & 7;
                const uint32_t dst = sbuf + (uint32_t)mat * 16384
                                   + (uint32_t)row * 128 + (uint32_t)((g ^ (row & 7)) << 4);
                cp16(dst, sp + (size_t)row * ld + k0 + g * 8);
            }
        }
        cp_commit();
    };

    // fragment address constants
    const int arow = lane & 15;          // row within m16 tile
    const int akhi = lane >> 4;          // 0/1 -> k+8 half
    const int brow = lane & 7;
    const int bkhi = (lane >> 3) & 1;
    const uint32_t aRowOff = (uint32_t)(wm * 64 + arow) * 128;
    const uint32_t bRowOff = (uint32_t)(wn * 32 + brow) * 128 + 32768u;

    load_stage(0);

    for (int t = 0; t < T; t++) {
        if (t + 1 < T) { load_stage(t + 1); cp_wait<1>(); }
        else          { cp_wait<0>(); }
        __syncthreads();

        const uint32_t sbuf = sb + (t & 1) * STAGE_BYTES;
        #pragma unroll
        for (int k16 = 0; k16 < 4; k16++) {
            const uint32_t aSw = (uint32_t)(((k16 * 2 + akhi) ^ (arow & 7)) << 4);
            const uint32_t bSw = (uint32_t)(((k16 * 2 + bkhi) ^ brow) << 4);

            uint32_t ah[4][4], al[4][4], bh[4][2], bl[4][2];
            #pragma unroll
            for (int i = 0; i < 4; i++) {
                const uint32_t ad = sbuf + aRowOff + (uint32_t)(i * 16 * 128) + aSw;
                ldsm4(ah[i], ad);
                ldsm4(al[i], ad + 16384u);
            }
            #pragma unroll
            for (int j = 0; j < 4; j++) {
                const uint32_t bd = sbuf + bRowOff + (uint32_t)(j * 8 * 128) + bSw;
                ldsm2(bh[j], bd);
                ldsm2(bl[j], bd + 16384u);
            }
            #pragma unroll
            for (int i = 0; i < 4; i++)
                #pragma unroll
                for (int j = 0; j < 4; j++) {
                    mma16816(acc[i][j], ah[i], bh[j]);
                    mma16816(acc[i][j], ah[i], bl[j]);
                    mma16816(acc[i][j], al[i], bh[j]);
                }
        }
        __syncthreads();
    }

    // ---------------- epilogue ----------------
    const int rbase = m0 + wm * 64 + (lane >> 2);
    const int cbase = n0 + wn * 32 + (lane & 3) * 2;

    float bc0[4], bc1[4];
    if (EPI == 0) {
        #pragma unroll
        for (int j = 0; j < 4; j++) { bc0[j] = bias[cbase + j * 8]; bc1[j] = bias[cbase + j * 8 + 1]; }
    }

    #pragma unroll
    for (int i = 0; i < 4; i++) {
        const int row0 = rbase + i * 16, row1 = row0 + 8;
        float br0 = 0.f, br1 = 0.f;
        if (EPI == 1 || EPI == 4) { br0 = bias[row0]; br1 = bias[row1]; }
        #pragma unroll
        for (int j = 0; j < 4; j++) {
            const int col = cbase + j * 8;
            const size_t ob0 = (size_t)b * oBatch + (size_t)row0 * ldO + col;
            const size_t ob1 = (size_t)b * oBatch + (size_t)row1 * ldO + col;
            float v0 = acc[i][j][0], v1 = acc[i][j][1];
            float v2 = acc[i][j][2], v3 = acc[i][j][3];
            if (EPI == 2) {
                *(float2*)(outF + ob0) = make_float2(v0 * SCALE, v1 * SCALE);
                *(float2*)(outF + ob1) = make_float2(v2 * SCALE, v3 * SCALE);
            } else if (EPI == 4) {
                float2 r0 = *(const float2*)(resid + ob0);
                float2 r1 = *(const float2*)(resid + ob1);
                *(float2*)(outF + ob0) = make_float2(v0 + br0 + r0.x, v1 + br0 + r0.y);
                *(float2*)(outF + ob1) = make_float2(v2 + br1 + r1.x, v3 + br1 + r1.y);
            } else {
                if (EPI == 0) { v0 += bc0[j]; v1 += bc1[j]; v2 += bc0[j]; v3 += bc1[j]; }
                if (EPI == 1) { v0 += br0;    v1 += br0;    v2 += br1;    v3 += br1;   }
                __nv_bfloat16 h0, l0, h1, l1, h2, l2, h3, l3;
                split2(v0, h0, l0); split2(v1, h1, l1);
                split2(v2, h2, l2); split2(v3, h3, l3);
                *(__nv_bfloat162*)(outH + ob0) = __nv_bfloat162(h0, h1);
                *(__nv_bfloat162*)(outL + ob0) = __nv_bfloat162(l0, l1);
                *(__nv_bfloat162*)(outH + ob1) = __nv_bfloat162(h2, h3);
                *(__nv_bfloat162*)(outL + ob1) = __nv_bfloat162(l2, l3);
            }
        }
    }
}

// ---------------------------------------------------------------------------
// Softmax: read fp32 scores row, write split bf16 attn.
// ---------------------------------------------------------------------------
__global__ void softmax_kernel() {
    const size_t rbase = (size_t)blockIdx.x * NN_;
    const float4* __restrict__ row = (const float4*)(g_s + rbase);
    float4 v = row[threadIdx.x];

    float m = fmaxf(fmaxf(v.x, v.y), fmaxf(v.z, v.w));
    #pragma unroll
    for (int o = 16; o; o >>= 1) m = fmaxf(m, __shfl_xor_sync(0xffffffffu, m, o));
    __shared__ float shm[8], shs[8];
    if ((threadIdx.x & 31) == 0) shm[threadIdx.x >> 5] = m;
    __syncthreads();
    float M = shm[0];
    #pragma unroll
    for (int i = 1; i < 8; i++) M = fmaxf(M, shm[i]);

    v.x = __expf(v.x - M); v.y = __expf(v.y - M);
    v.z = __expf(v.z - M); v.w = __expf(v.w - M);
    float s = v.x + v.y + v.z + v.w;
    #pragma unroll
    for (int o = 16; o; o >>= 1) s += __shfl_xor_sync(0xffffffffu, s, o);
    if ((threadIdx.x & 31) == 0) shs[threadIdx.x >> 5] = s;
    __syncthreads();
    float S = 0.f;
    #pragma unroll
    for (int i = 0; i < 8; i++) S += shs[i];
    const float r = 1.f / S;

    __align__(8) __nv_bfloat16 hh[4], ll[4];
    split2(v.x * r, hh[0], ll[0]);
    split2(v.y * r, hh[1], ll[1]);
    split2(v.z * r, hh[2], ll[2]);
    split2(v.w * r, hh[3], ll[3]);
    const size_t o = rbase + threadIdx.x * 4;
    *(uint2*)(g_ah + o) = *(uint2*)hh;
    *(uint2*)(g_al + o) = *(uint2*)ll;
}

// ---------------------------------------------------------------------------
// Launch
// ---------------------------------------------------------------------------
extern "C" void kernel_launch(void* const* d_in, const int* in_sizes, int n_in,
                              void* d_out, int out_size) {
    const float* x      = (const float*)d_in[0];
    const float* gamma  = (const float*)d_in[1];
    const float* beta   = (const float*)d_in[2];
    const float* w_qkv  = (const float*)d_in[3];
    const float* b_qkv  = (const float*)d_in[4];
    const float* w_proj = (const float*)d_in[5];
    const float* b_proj = (const float*)d_in[6];
    float* y = (float*)d_out;

    cudaFuncSetAttribute(gemm_bb<0>, cudaFuncAttributeMaxDynamicSharedMemorySize, SMEM_BYTES);
    cudaFuncSetAttribute(gemm_bb<1>, cudaFuncAttributeMaxDynamicSharedMemorySize, SMEM_BYTES);
    cudaFuncSetAttribute(gemm_bb<2>, cudaFuncAttributeMaxDynamicSharedMemorySize, SMEM_BYTES);
    cudaFuncSetAttribute(gemm_bb<3>, cudaFuncAttributeMaxDynamicSharedMemorySize, SMEM_BYTES);
    cudaFuncSetAttribute(gemm_bb<4>, cudaFuncAttributeMaxDynamicSharedMemorySize, SMEM_BYTES);

    __nv_bfloat16 *xnh, *xnl, *wqh, *wql, *wph, *wpl, *qkth, *qktl, *vh, *vl, *ah, *al, *avh, *avl;
    float* sbuf;
    cudaGetSymbolAddress((void**)&xnh,  g_xnh);  cudaGetSymbolAddress((void**)&xnl,  g_xnl);
    cudaGetSymbolAddress((void**)&wqh,  g_wqh);  cudaGetSymbolAddress((void**)&wql,  g_wql);
    cudaGetSymbolAddress((void**)&wph,  g_wph);  cudaGetSymbolAddress((void**)&wpl,  g_wpl);
    cudaGetSymbolAddress((void**)&qkth, g_qkth); cudaGetSymbolAddress((void**)&qktl, g_qktl);
    cudaGetSymbolAddress((void**)&vh,   g_vh);   cudaGetSymbolAddress((void**)&vl,   g_vl);
    cudaGetSymbolAddress((void**)&ah,   g_ah);   cudaGetSymbolAddress((void**)&al,   g_al);
    cudaGetSymbolAddress((void**)&avh,  g_avh);  cudaGetSymbolAddress((void**)&avl,  g_avl);
    cudaGetSymbolAddress((void**)&sbuf, g_s);

    split_kernel<<<(3 * CC * CC + 255) / 256, 256>>>(w_qkv, wqh, wql, 3 * CC * CC);
    split_kernel<<<(CC * CC + 255) / 256, 256>>>(w_proj, wph, wpl, CC * CC);

    gn_kernel<<<BB * 32, 256>>>(x, gamma, beta);

    // QK: D[n][o] = sum_c xn_t[n][c] * Wqk[o][c] + b_qkv[o]   (M=1024, N=1024, K=512)
    gemm_bb<0><<<dim3(8, 8, BB), 256, SMEM_BYTES>>>(
        xnh, xnl, (size_t)NN_ * CC, CC,
        wqh, wql, 0, CC, CC,
        qkth, qktl, nullptr, (size_t)NN_ * NN_, NN_, b_qkv, nullptr);

    // V: D[o][n] = sum_c Wv[o][c] * xn_t[n][c] + b_qkv[1024+o]  (M=512, N=1024, K=512)
    gemm_bb<1><<<dim3(8, 4, BB), 256, SMEM_BYTES>>>(
        wqh + (size_t)2 * CC * CC, wql + (size_t)2 * CC * CC, 0, CC,
        xnh, xnl, (size_t)NN_ * CC, CC, CC,
        vh, vl, nullptr, (size_t)CC * NN_, NN_, b_qkv + 2 * CC, nullptr);

    // Scores: D[i][j] = SCALE * sum_c q_t[i][c] * k_t[j][c]     (M=1024, N=1024, K=512)
    gemm_bb<2><<<dim3(8, 8, BB), 256, SMEM_BYTES>>>(
        qkth, qktl, (size_t)NN_ * NN_, NN_,
        qkth + CC, qktl + CC, (size_t)NN_ * NN_, NN_, CC,
        nullptr, nullptr, sbuf, (size_t)NN_ * NN_, NN_, nullptr, nullptr);

    softmax_kernel<<<BB * NN_, 256>>>();

    // AV: D[i][c] = sum_j attn[i][j] * v[c][j]                  (M=1024, N=512, K=1024)
    gemm_bb<3><<<dim3(4, 8, BB), 256, SMEM_BYTES>>>(
        ah, al, (size_t)NN_ * NN_, NN_,
        vh, vl, (size_t)CC * NN_, NN_, NN_,
        avh, avl, nullptr, (size_t)NN_ * CC, CC, nullptr, nullptr);

    // Proj: y[o][n] = x[o][n] + b_proj[o] + sum_c Wp[o][c] * av_t[n][c] (M=512, N=1024, K=512)
    gemm_bb<4><<<dim3(8, 4, BB), 256, SMEM_BYTES>>>(
        wph, wpl, 0, CC,
        avh, avl, (size_t)NN_ * CC, CC, CC,
        nullptr, nullptr, y, (size_t)CC * NN_, NN_, b_proj, x);
}

// round 4
// speedup vs baseline: 6.8084x; 1.8704x over previous
#include <cuda_runtime.h>
#include <cuda_fp16.h>
#include <math.h>
#include <stdint.h>

// Problem constants: B=16, C=512, H=W=32, GROUPS=32
#define BB   16
#define CC   512
#define NN_  1024
#define CG   16
#define SCALE 0.044194173824159216f   // 512^-0.5

// ---------------------------------------------------------------------------
// Scratch (device globals)
// ---------------------------------------------------------------------------
__device__ __align__(128) __half g_xn [(size_t)BB * NN_ * CC];   // xn_t [b][n][c]
__device__ __align__(128) __half g_wq [(size_t)3 * CC * CC];     // w_qkv fp16
__device__ __align__(128) __half g_wp [(size_t)CC * CC];         // w_proj fp16
__device__ __align__(128) __half g_qkt[(size_t)BB * NN_ * NN_];  // [b][n][o] (q|k)
__device__ __align__(128) __half g_v  [(size_t)BB * CC * NN_];   // v [b][c][n]
__device__ __align__(128) float  g_s  [(size_t)BB * NN_ * NN_];  // scores fp32
__device__ __align__(128) __half g_a  [(size_t)BB * NN_ * NN_];  // attn fp16
__device__ __align__(128) __half g_av [(size_t)BB * NN_ * CC];   // av_t [b][n][c]

// ---------------------------------------------------------------------------
// Helpers (base-target sm_80+ only)
// ---------------------------------------------------------------------------
__device__ __forceinline__ uint32_t smem_u32(const void* p) {
    uint32_t a;
    asm("{ .reg .u64 t; cvta.to.shared.u64 t, %1; cvt.u32.u64 %0, t; }" : "=r"(a) : "l"(p));
    return a;
}
__device__ __forceinline__ void ldsm4(uint32_t (&r)[4], uint32_t addr) {
    asm volatile("ldmatrix.sync.aligned.m8n8.x4.shared.b16 {%0,%1,%2,%3}, [%4];"
        : "=r"(r[0]), "=r"(r[1]), "=r"(r[2]), "=r"(r[3]) : "r"(addr));
}
__device__ __forceinline__ void ldsm2(uint32_t (&r)[2], uint32_t addr) {
    asm volatile("ldmatrix.sync.aligned.m8n8.x2.shared.b16 {%0,%1}, [%2];"
        : "=r"(r[0]), "=r"(r[1]) : "r"(addr));
}
__device__ __forceinline__ void mma16816(float (&c)[4], const uint32_t (&a)[4],
                                         const uint32_t (&b)[2]) {
    asm volatile("mma.sync.aligned.m16n8k16.row.col.f32.f16.f16.f32 "
        "{%0,%1,%2,%3}, {%4,%5,%6,%7}, {%8,%9}, {%0,%1,%2,%3};"
        : "+f"(c[0]), "+f"(c[1]), "+f"(c[2]), "+f"(c[3])
        : "r"(a[0]), "r"(a[1]), "r"(a[2]), "r"(a[3]), "r"(b[0]), "r"(b[1]));
}
__device__ __forceinline__ void cp16(uint32_t dst, const void* src) {
    asm volatile("cp.async.cg.shared.global [%0], [%1], 16;" :: "r"(dst), "l"(src));
}
__device__ __forceinline__ void cp_commit() {
    asm volatile("cp.async.commit_group;" ::: "memory");
}
template<int N> __device__ __forceinline__ void cp_wait() {
    asm volatile("cp.async.wait_group %0;" :: "n"(N) : "memory");
}

// ---------------------------------------------------------------------------
// fp32 -> fp16 convert
// ---------------------------------------------------------------------------
__global__ void cvt_kernel(const float* __restrict__ src, __half* __restrict__ dst, int n) {
    int i = blockIdx.x * blockDim.x + threadIdx.x;
    if (i < n) dst[i] = __float2half_rn(src[i]);
}

// ---------------------------------------------------------------------------
// GroupNorm -> transposed fp16 output xn_t[b][n][c]
// ---------------------------------------------------------------------------
__global__ void gn_kernel(const float* __restrict__ x,
                          const float* __restrict__ gamma,
                          const float* __restrict__ beta) {
    const int b = blockIdx.x >> 5;
    const int g = blockIdx.x & 31;
    const size_t base = ((size_t)b * CC + (size_t)g * CG) * NN_;
    const float4* __restrict__ x4 = (const float4*)(x + base);

    float s = 0.f, s2 = 0.f;
    for (int i = threadIdx.x; i < CG * NN_ / 4; i += 256) {
        float4 v = x4[i];
        s  += v.x + v.y + v.z + v.w;
        s2 += v.x * v.x + v.y * v.y + v.z * v.z + v.w * v.w;
    }
    #pragma unroll
    for (int o = 16; o; o >>= 1) {
        s  += __shfl_down_sync(0xffffffffu, s,  o);
        s2 += __shfl_down_sync(0xffffffffu, s2, o);
    }
    __shared__ float2 sh[8];
    __shared__ float sga[16], sbe[16];
    if ((threadIdx.x & 31) == 0) sh[threadIdx.x >> 5] = make_float2(s, s2);
    __syncthreads();
    if (threadIdx.x < 16) {
        float ts = 0.f, ts2 = 0.f;
        #pragma unroll
        for (int i = 0; i < 8; i++) { ts += sh[i].x; ts2 += sh[i].y; }
        const float inv = 1.f / (float)(CG * NN_);
        float mu  = ts * inv;
        float var = ts2 * inv - mu * mu;
        float rstd = rsqrtf(var + 1e-5f);
        int c = g * CG + threadIdx.x;
        float ga = gamma[c] * rstd;
        sga[threadIdx.x] = ga;
        sbe[threadIdx.x] = beta[c] - mu * ga;
    }
    __syncthreads();

    for (int n = threadIdx.x; n < NN_; n += 256) {
        __align__(16) __half hh[16];
        #pragma unroll
        for (int c = 0; c < 16; c++) {
            float v = x[base + (size_t)c * NN_ + n];
            hh[c] = __float2half_rn(v * sga[c] + sbe[c]);
        }
        size_t o = ((size_t)(b * NN_ + n)) * CC + g * CG;
        *(uint4*)(g_xn + o)     = *(uint4*)(hh);
        *(uint4*)(g_xn + o + 8) = *(uint4*)(hh + 8);
    }
}

// ---------------------------------------------------------------------------
// fp16 HMMA GEMM:  D[M,N] = sum_k A[m][k] * B[n][k]   (both K-major)
// CTA tile 128x128, BK=64 (128B rows, XOR swizzle), 8 warps (64x32 each),
// 3-stage cp.async ring, 2 CTAs/SM.
// EPI: 0=fp16+col bias, 1=fp16+row bias, 2=fp32*SCALE, 3=fp16, 4=fp32+row bias+resid
// ---------------------------------------------------------------------------
#define STAGE_BYTES 32768              // A 16KB + B 16KB
#define NSTAGE      3
#define SMEM_BYTES  (NSTAGE * STAGE_BYTES)

template<int EPI>
__global__ void __launch_bounds__(256, 2) gemm_hh(
    const __half* __restrict__ A, size_t aBatch, int ldA,
    const __half* __restrict__ B, size_t bBatch, int ldB,
    int K,
    __half* __restrict__ outH, float* __restrict__ outF,
    size_t oBatch, int ldO,
    const float* __restrict__ bias, const float* __restrict__ resid)
{
    extern __shared__ char smem[];
    const uint32_t sb = smem_u32(smem);

    const int tid = threadIdx.x, lane = tid & 31, wid = tid >> 5;
    const int wm = wid >> 2, wn = wid & 3;       // 2 x 4 warp grid -> 64x32 warp tile
    const int b  = blockIdx.z;
    const int m0 = blockIdx.y * 128, n0 = blockIdx.x * 128;

    const __half* srcA = A + (size_t)b * aBatch + (size_t)m0 * ldA;
    const __half* srcB = B + (size_t)b * bBatch + (size_t)n0 * ldB;

    float acc[4][4][4];
    #pragma unroll
    for (int i = 0; i < 4; i++)
        #pragma unroll
        for (int j = 0; j < 4; j++)
            #pragma unroll
            for (int q = 0; q < 4; q++) acc[i][j][q] = 0.f;

    const int T = K / 64;

    // loader: per stage 2 matrices x 1024 16B-chunks; 8 chunks/thread
    const int l_row = tid >> 1;                 // 0..127 (2 threads per row, 4 chunks each)
    const int l_g0  = (tid & 1) * 4;            // chunk col 0..3 or 4..7
    auto load_stage = [&](int t) {
        const int k0 = t * 64;
        const uint32_t sbuf = sb + (uint32_t)(t % NSTAGE) * STAGE_BYTES;
        const uint32_t rowOff = (uint32_t)l_row * 128;
        #pragma unroll
        for (int q = 0; q < 4; q++) {
            const int g = l_g0 + q;
            const uint32_t sw = (uint32_t)((g ^ (l_row & 7)) << 4);
            cp16(sbuf + rowOff + sw,          srcA + (size_t)l_row * ldA + k0 + g * 8);
            cp16(sbuf + 16384 + rowOff + sw,  srcB + (size_t)l_row * ldB + k0 + g * 8);
        }
    };

    // fragment address constants
    const int arow = lane & 15;
    const int akhi = lane >> 4;
    const int brow = lane & 7;
    const int bkhi = (lane >> 3) & 1;
    const uint32_t aRowOff = (uint32_t)(wm * 64 + arow) * 128;
    const uint32_t bRowOff = (uint32_t)(wn * 32 + brow) * 128 + 16384u;

    load_stage(0); cp_commit();
    load_stage(1); cp_commit();

    for (int t = 0; t < T; t++) {
        cp_wait<1>();                       // stage t resident
        __syncthreads();                    // everyone done reading slot (t-1)%3
        if (t + 2 < T) load_stage(t + 2);   // refill slot (t+2)%3
        cp_commit();                        // always commit (keeps group numbering)

        const uint32_t sbuf = sb + (uint32_t)(t % NSTAGE) * STAGE_BYTES;
        #pragma unroll
        for (int k16 = 0; k16 < 4; k16++) {
            const uint32_t aSw = (uint32_t)(((k16 * 2 + akhi) ^ (arow & 7)) << 4);
            const uint32_t bSw = (uint32_t)(((k16 * 2 + bkhi) ^ brow) << 4);
            uint32_t af[4][4], bf[4][2];
            #pragma unroll
            for (int i = 0; i < 4; i++)
                ldsm4(af[i], sbuf + aRowOff + (uint32_t)(i * 16 * 128) + aSw);
            #pragma unroll
            for (int j = 0; j < 4; j++)
                ldsm2(bf[j], sbuf + bRowOff + (uint32_t)(j * 8 * 128) + bSw);
            #pragma unroll
            for (int i = 0; i < 4; i++)
                #pragma unroll
                for (int j = 0; j < 4; j++)
                    mma16816(acc[i][j], af[i], bf[j]);
        }
        __syncthreads();
    }

    // ---------------- epilogue ----------------
    const int rbase = m0 + wm * 64 + (lane >> 2);
    const int cbase = n0 + wn * 32 + (lane & 3) * 2;

    float bc0[4], bc1[4];
    if (EPI == 0) {
        #pragma unroll
        for (int j = 0; j < 4; j++) { bc0[j] = bias[cbase + j * 8]; bc1[j] = bias[cbase + j * 8 + 1]; }
    }

    #pragma unroll
    for (int i = 0; i < 4; i++) {
        const int row0 = rbase + i * 16, row1 = row0 + 8;
        float br0 = 0.f, br1 = 0.f;
        if (EPI == 1 || EPI == 4) { br0 = bias[row0]; br1 = bias[row1]; }
        #pragma unroll
        for (int j = 0; j < 4; j++) {
            const int col = cbase + j * 8;
            const size_t ob0 = (size_t)b * oBatch + (size_t)row0 * ldO + col;
            const size_t ob1 = (size_t)b * oBatch + (size_t)row1 * ldO + col;
            float v0 = acc[i][j][0], v1 = acc[i][j][1];
            float v2 = acc[i][j][2], v3 = acc[i][j][3];
            if (EPI == 2) {
                *(float2*)(outF + ob0) = make_float2(v0 * SCALE, v1 * SCALE);
                *(float2*)(outF + ob1) = make_float2(v2 * SCALE, v3 * SCALE);
            } else if (EPI == 4) {
                float2 r0 = *(const float2*)(resid + ob0);
                float2 r1 = *(const float2*)(resid + ob1);
                *(float2*)(outF + ob0) = make_float2(v0 + br0 + r0.x, v1 + br0 + r0.y);
                *(float2*)(outF + ob1) = make_float2(v2 + br1 + r1.x, v3 + br1 + r1.y);
            } else {
                if (EPI == 0) { v0 += bc0[j]; v1 += bc1[j]; v2 += bc0[j]; v3 += bc1[j]; }
                if (EPI == 1) { v0 += br0;    v1 += br0;    v2 += br1;    v3 += br1;   }
                *(__half2*)(outH + ob0) = __floats2half2_rn(v0, v1);
                *(__half2*)(outH + ob1) = __floats2half2_rn(v2, v3);
            }
        }
    }
}

// ---------------------------------------------------------------------------
// Softmax: read fp32 scores row, write fp16 attn.
// ---------------------------------------------------------------------------
__global__ void softmax_kernel() {
    const size_t rbase = (size_t)blockIdx.x * NN_;
    const float4* __restrict__ row = (const float4*)(g_s + rbase);
    float4 v = row[threadIdx.x];

    float m = fmaxf(fmaxf(v.x, v.y), fmaxf(v.z, v.w));
    #pragma unroll
    for (int o = 16; o; o >>= 1) m = fmaxf(m, __shfl_xor_sync(0xffffffffu, m, o));
    __shared__ float shm[8], shs[8];
    if ((threadIdx.x & 31) == 0) shm[threadIdx.x >> 5] = m;
    __syncthreads();
    float M = shm[0];
    #pragma unroll
    for (int i = 1; i < 8; i++) M = fmaxf(M, shm[i]);

    v.x = __expf(v.x - M); v.y = __expf(v.y - M);
    v.z = __expf(v.z - M); v.w = __expf(v.w - M);
    float s = v.x + v.y + v.z + v.w;
    #pragma unroll
    for (int o = 16; o; o >>= 1) s += __shfl_xor_sync(0xffffffffu, s, o);
    if ((threadIdx.x & 31) == 0) shs[threadIdx.x >> 5] = s;
    __syncthreads();
    float S = 0.f;
    #pragma unroll
    for (int i = 0; i < 8; i++) S += shs[i];
    const float r = 1.f / S;

    __align__(8) __half2 hh[2];
    hh[0] = __floats2half2_rn(v.x * r, v.y * r);
    hh[1] = __floats2half2_rn(v.z * r, v.w * r);
    *(uint2*)(g_a + rbase + threadIdx.x * 4) = *(uint2*)hh;
}

// ---------------------------------------------------------------------------
// Launch
// ---------------------------------------------------------------------------
extern "C" void kernel_launch(void* const* d_in, const int* in_sizes, int n_in,
                              void* d_out, int out_size) {
    const float* x      = (const float*)d_in[0];
    const float* gamma  = (const float*)d_in[1];
    const float* beta   = (const float*)d_in[2];
    const float* w_qkv  = (const float*)d_in[3];
    const float* b_qkv  = (const float*)d_in[4];
    const float* w_proj = (const float*)d_in[5];
    const float* b_proj = (const float*)d_in[6];
    float* y = (float*)d_out;

    cudaFuncSetAttribute(gemm_hh<0>, cudaFuncAttributeMaxDynamicSharedMemorySize, SMEM_BYTES);
    cudaFuncSetAttribute(gemm_hh<1>, cudaFuncAttributeMaxDynamicSharedMemorySize, SMEM_BYTES);
    cudaFuncSetAttribute(gemm_hh<2>, cudaFuncAttributeMaxDynamicSharedMemorySize, SMEM_BYTES);
    cudaFuncSetAttribute(gemm_hh<3>, cudaFuncAttributeMaxDynamicSharedMemorySize, SMEM_BYTES);
    cudaFuncSetAttribute(gemm_hh<4>, cudaFuncAttributeMaxDynamicSharedMemorySize, SMEM_BYTES);

    __half *xn, *wq, *wp, *qkt, *v, *a, *av;
    float* sbuf;
    cudaGetSymbolAddress((void**)&xn,  g_xn);
    cudaGetSymbolAddress((void**)&wq,  g_wq);
    cudaGetSymbolAddress((void**)&wp,  g_wp);
    cudaGetSymbolAddress((void**)&qkt, g_qkt);
    cudaGetSymbolAddress((void**)&v,   g_v);
    cudaGetSymbolAddress((void**)&a,   g_a);
    cudaGetSymbolAddress((void**)&av,  g_av);
    cudaGetSymbolAddress((void**)&sbuf, g_s);

    cvt_kernel<<<(3 * CC * CC + 255) / 256, 256>>>(w_qkv, wq, 3 * CC * CC);
    cvt_kernel<<<(CC * CC + 255) / 256, 256>>>(w_proj, wp, CC * CC);

    gn_kernel<<<BB * 32, 256>>>(x, gamma, beta);

    // QK: D[n][o] = sum_c xn_t[n][c] * Wqk[o][c] + b_qkv[o]   (M=1024, N=1024, K=512)
    gemm_hh<0><<<dim3(8, 8, BB), 256, SMEM_BYTES>>>(
        xn, (size_t)NN_ * CC, CC,
        wq, 0, CC, CC,
        qkt, nullptr, (size_t)NN_ * NN_, NN_, b_qkv, nullptr);

    // V: D[o][n] = sum_c Wv[o][c] * xn_t[n][c] + b_qkv[1024+o]  (M=512, N=1024, K=512)
    gemm_hh<1><<<dim3(8, 4, BB), 256, SMEM_BYTES>>>(
        wq + (size_t)2 * CC * CC, 0, CC,
        xn, (size_t)NN_ * CC, CC, CC,
        v, nullptr, (size_t)CC * NN_, NN_, b_qkv + 2 * CC, nullptr);

    // Scores: D[i][j] = SCALE * sum_c q_t[i][c] * k_t[j][c]     (M=1024, N=1024, K=512)
    gemm_hh<2><<<dim3(8, 8, BB), 256, SMEM_BYTES>>>(
        qkt, (size_t)NN_ * NN_, NN_,
        qkt + CC, (size_t)NN_ * NN_, NN_, CC,
        nullptr, sbuf, (size_t)NN_ * NN_, NN_, nullptr, nullptr);

    softmax_kernel<<<BB * NN_, 256>>>();

    // AV: D[i][c] = sum_j attn[i][j] * v[c][j]                  (M=1024, N=512, K=1024)
    gemm_hh<3><<<dim3(4, 8, BB), 256, SMEM_BYTES>>>(
        a, (size_t)NN_ * NN_, NN_,
        v, (size_t)CC * NN_, NN_, NN_,
        av, nullptr, (size_t)NN_ * CC, CC, nullptr, nullptr);

    // Proj: y[o][n] = x[o][n] + b_proj[o] + sum_c Wp[o][c] * av_t[n][c] (M=512, N=1024, K=512)
    gemm_hh<4><<<dim3(8, 4, BB), 256, SMEM_BYTES>>>(
        wp, 0, CC,
        av, (size_t)NN_ * CC, CC, CC,
        nullptr, y, (size_t)CC * NN_, NN_, b_proj, x);
}